// round 1
// baseline (speedup 1.0000x reference)
#include <cuda_runtime.h>
#include <cuda_bf16.h>

#define D 4096
#define LOGD 12
#define THREADS 256
#define REGS 16

// swizzled physical index in shared: bank = (A^B) | ((B0^C0)<<4),
// conflict-free for all three access patterns used below.
__device__ __forceinline__ int sw(int i) {
    return i ^ ((i >> 4) & 31);
}

// 16-point in-register FWHT (4 butterfly stages), fully unrolled.
__device__ __forceinline__ void fwht16(float r[REGS]) {
#pragma unroll
    for (int h = 1; h < 16; h <<= 1) {
#pragma unroll
        for (int j = 0; j < 16; j++) {
            if (!(j & h)) {
                float a = r[j];
                float b = r[j | h];
                r[j] = a + b;
                r[j | h] = a - b;
            }
        }
    }
}

__global__ __launch_bounds__(THREADS, 8)
void rht_kernel(const float* __restrict__ x,
                const float* __restrict__ signs,
                float* __restrict__ out) {
    __shared__ float s[D];

    const int row = blockIdx.x;
    const int t   = threadIdx.x;

    const float* __restrict__ xr = x + (size_t)row * D;
    float*       __restrict__ orow = out + (size_t)row * D;

    float r[REGS];

    // ---------------- Pass 1: stages over bits A (0..3) ----------------
    // Thread t owns contiguous elements [t*16, t*16+16): vectorized float4 loads.
    const int base = t * REGS;
    const float4* xv4 = reinterpret_cast<const float4*>(xr + base);
    const float4* sv4 = reinterpret_cast<const float4*>(signs + base);
#pragma unroll
    for (int q = 0; q < 4; q++) {
        float4 xv = xv4[q];
        float4 sv = sv4[q];
        r[q * 4 + 0] = xv.x * sv.x;
        r[q * 4 + 1] = xv.y * sv.y;
        r[q * 4 + 2] = xv.z * sv.z;
        r[q * 4 + 3] = xv.w * sv.w;
    }
    fwht16(r);
#pragma unroll
    for (int a = 0; a < 16; a++) {
        s[sw(base + a)] = r[a];
    }
    __syncthreads();

    // ---------------- Pass 2: stages over bits B (4..7) ----------------
    // Thread t = (C<<4)|A gathers i = A | (k<<4) | (C<<8), k = register idx.
    const int A = t & 15;
    const int C = t >> 4;
#pragma unroll
    for (int k = 0; k < 16; k++) {
        r[k] = s[sw(A | (k << 4) | (C << 8))];
    }
    fwht16(r);
    // each thread writes back only its own 16 slots -> no sync needed between
    // this write and its own read above; one sync before pass 3 readers.
#pragma unroll
    for (int k = 0; k < 16; k++) {
        s[sw(A | (k << 4) | (C << 8))] = r[k];
    }
    __syncthreads();

    // ---------------- Pass 3: stages over bits C (8..11) ----------------
    // Thread t = (B<<4)|A gathers i = A | (B<<4) | (k<<8).
    const int B = t >> 4;
#pragma unroll
    for (int k = 0; k < 16; k++) {
        r[k] = s[sw(A | (B << 4) | (k << 8))];
    }
    fwht16(r);
    // normalize by D^-1/2 = 1/64 and store.
    // per k, a warp writes 32 contiguous floats -> 128B coalesced transactions.
#pragma unroll
    for (int k = 0; k < 16; k++) {
        orow[A | (B << 4) | (k << 8)] = r[k] * 0.015625f;
    }
}

extern "C" void kernel_launch(void* const* d_in, const int* in_sizes, int n_in,
                              void* d_out, int out_size) {
    const float* x     = (const float*)d_in[0];
    const float* signs = (const float*)d_in[1];
    float* out = (float*)d_out;

    const int n_rows = in_sizes[0] / D;  // 8192
    rht_kernel<<<n_rows, THREADS>>>(x, signs, out);
}

// round 2
// speedup vs baseline: 1.2892x; 1.2892x over previous
#include <cuda_runtime.h>
#include <cuda_bf16.h>

#define D 4096
#define THREADS 256

// GF(2)-linear bank swizzle. bank = i[4:0] XOR g(i[8:5]) with
//   i5 -> b1, i6 -> {b2,b0}, i7 -> {b3,b0}, i8 -> {b4,b0}
// This is injective on each pass's lane-varying bit sets:
//   pass1 lanes vary i{2..6}, pass2 lanes vary i{0,1,6,7,8},
//   pass3 lanes vary i{0..4}  -> conflict-free for every LDS/STS below.
// g only touches bits 0-4 and depends on bits 5-8 => bijection on [0,4096).
__device__ __forceinline__ int swz(int i) {
    int h = (i >> 5) & 15;                       // (i5,i6,i7,i8)
    int g = ((h & 1) << 1)                       // i5 -> bit1
          ^ ((h >> 1) << 2)                      // i6,i7,i8 -> bits 2,3,4
          ^ (((h >> 1) ^ (h >> 2) ^ (h >> 3)) & 1); // i6^i7^i8 -> bit0
    return i ^ g;
}

// 16-point in-register FWHT (4 butterfly stages), fully unrolled.
// Register index bit k corresponds to whichever global bit the caller mapped it to.
__device__ __forceinline__ void fwht16(float r[16]) {
#pragma unroll
    for (int h = 1; h < 16; h <<= 1) {
#pragma unroll
        for (int j = 0; j < 16; j++) {
            if (!(j & h)) {
                float a = r[j];
                float b = r[j | h];
                r[j] = a + b;
                r[j | h] = a - b;
            }
        }
    }
}

__global__ __launch_bounds__(THREADS, 8)
void rht_kernel(const float* __restrict__ x,
                const float* __restrict__ signs,
                float* __restrict__ out) {
    __shared__ float s[D];

    const int row = blockIdx.x;
    const int t   = threadIdx.x;

    float r[16];

    // ------- Pass 1: bits {0,1,10,11}. Thread t fixes i[9:2] = t. -------
    // float4 loads at i = h*1024 + t*4 : lane-contiguous, fully coalesced
    // for BOTH x and signs (4 wavefronts per warp-op, the minimum).
    const float4* __restrict__ xv4 = reinterpret_cast<const float4*>(x + (size_t)row * D);
    const float4* __restrict__ sv4 = reinterpret_cast<const float4*>(signs);
#pragma unroll
    for (int h = 0; h < 4; h++) {
        float4 xv = xv4[(h << 8) + t];
        float4 sv = sv4[(h << 8) + t];
        r[h * 4 + 0] = xv.x * sv.x;   // reg bits: j -> i{0,1}, h -> i{10,11}
        r[h * 4 + 1] = xv.y * sv.y;
        r[h * 4 + 2] = xv.z * sv.z;
        r[h * 4 + 3] = xv.w * sv.w;
    }
    fwht16(r);
#pragma unroll
    for (int h = 0; h < 4; h++) {
#pragma unroll
        for (int j = 0; j < 4; j++) {
            s[swz((h << 10) | (t << 2) | j)] = r[h * 4 + j];
        }
    }
    __syncthreads();

    // ------- Pass 2: bits {2,3,4,5}. Thread fixes i{0,1,6..11}. -------
    const int base2 = ((t >> 2) << 6) | (t & 3);
#pragma unroll
    for (int k = 0; k < 16; k++) {
        r[k] = s[swz(base2 | (k << 2))];
    }
    fwht16(r);
    // each thread writes back exactly the slots it read (disjoint across threads)
#pragma unroll
    for (int k = 0; k < 16; k++) {
        s[swz(base2 | (k << 2))] = r[k];
    }
    __syncthreads();

    // ------- Pass 3: bits {6,7,8,9}. Thread fixes i{0..5,10,11}. -------
    const int base3 = ((t >> 6) << 10) | (t & 63);
#pragma unroll
    for (int k = 0; k < 16; k++) {
        r[k] = s[swz(base3 | (k << 6))];
    }
    fwht16(r);

    // stores: lanes are contiguous in i[4:0] -> each scalar STG is a single
    // 128B coalesced transaction per warp. Normalize by D^-1/2 = 1/64.
    float* __restrict__ orow = out + (size_t)row * D;
#pragma unroll
    for (int k = 0; k < 16; k++) {
        orow[base3 | (k << 6)] = r[k] * 0.015625f;
    }
}

extern "C" void kernel_launch(void* const* d_in, const int* in_sizes, int n_in,
                              void* d_out, int out_size) {
    const float* x     = (const float*)d_in[0];
    const float* signs = (const float*)d_in[1];
    float* out = (float*)d_out;

    const int n_rows = in_sizes[0] / D;  // 8192
    rht_kernel<<<n_rows, THREADS>>>(x, signs, out);
}